// round 12
// baseline (speedup 1.0000x reference)
#include <cuda_runtime.h>

#define NTOT   32768      // 64 graphs * 512 nodes
#define NB     64
#define NPG    512
#define LIG    128
#define GN_PER_G 1020
#define GG_PER_G 2
#define GFIXPG (GN_PER_G + GG_PER_G)          // 1022
#define GFIX   (NB * GFIXPG)                  // 65408
#define FULL   0xffffffffu

// d = __fsqrt_rn(d2);  d <= 8  <=>  d2 <= 64+1ulp ;  d <= 10 <=> d2 <= 100+1ulp
#define T8_BITS  0x42800001
#define T10_BITS 0x42C80001

// Scratch (device globals; zero-initialized at load; d_arrive self-resets)
__device__ unsigned d_mask_ctx[NTOT * 16];
__device__ unsigned d_mask_inter[NTOT * 16];
__device__ int d_off_ctx[NTOT];     // within-graph exclusive row offsets
__device__ int d_off_inter[NTOT];
__device__ int d_graph_ctx[NB];
__device__ int d_graph_inter[NB];
__device__ int d_red_cnt[NB];
__device__ int d_arrive[NB];

__device__ __forceinline__ int warp_incl_scan(int x) {
    #pragma unroll
    for (int d = 1; d < 32; d <<= 1) {
        int y = __shfl_up_sync(FULL, x, d);
        if ((threadIdx.x & 31) >= d) x += y;
    }
    return x;
}

// One warp scans a 64-int array: exclusive prefix -> sh_excl[64], total -> *sh_tot.
__device__ __forceinline__ void warp_scan64_sh(const int* __restrict__ in,
                                               int* sh_excl, int* sh_tot) {
    int lane = threadIdx.x & 31;
    int v0 = in[2 * lane], v1 = in[2 * lane + 1];
    int s = v0 + v1;
    int x = warp_incl_scan(s);
    int excl = x - s;
    sh_excl[2 * lane]     = excl;
    sh_excl[2 * lane + 1] = excl + v0;
    if (lane == 31) *sh_tot = x;
}

// 32x32 bit-matrix transpose across a warp (lane = row of bit matrix).
__device__ __forceinline__ unsigned transpose32(unsigned x, int lane) {
    #pragma unroll
    for (int s = 16; s; s >>= 1) {
        unsigned m = (s == 16) ? 0x0000FFFFu : (s == 8) ? 0x00FF00FFu :
                     (s == 4)  ? 0x0F0F0F0Fu : (s == 2) ? 0x33333333u : 0x55555555u;
        unsigned q = __shfl_xor_sync(FULL, x, s);
        x = (lane & s) ? ((x & ~m) | ((q & ~m) >> s))
                       : ((x & m)  | ((q & m)  << s));
    }
    return x;
}

// Store word for (rowTile R, colWord C) with all boundary fixes applied.
__device__ __forceinline__ void store_word(unsigned w, int gbase, int R, int C, int lane) {
    if (C == 0 || C == 4) w &= ~1u;              // global columns 0 / 128
    if ((R == 0 || R == 4) && lane == 0) w = 0u; // global rows 0 / 128
    if (R == C) w &= ~(1u << lane);              // self pairs on diagonal
    int idx = ((gbase + R * 32 + lane) << 4) + C;
    if (R < 4 || C < 4) d_mask_inter[idx] = w;   // lig-lig tiles never reach here
    else                d_mask_ctx[idx]   = w;
}

// ---- count: symmetric tile-pair enumeration; 8 blocks x 256 thr per graph ----
__global__ void __launch_bounds__(256) count_kernel(const float* __restrict__ X) {
    __shared__ float4 s_pos[NPG];
    __shared__ int sw[8];
    __shared__ int s_last, s_red;
    int tid  = threadIdx.x, lane = tid & 31, wid = tid >> 5;
    int blk  = blockIdx.x;                     // 512 blocks, 8 per graph
    int b    = blk >> 3;
    int gbase = b << 9;
    int W    = (blk & 7) * 8 + wid;            // warp id within graph, 0..63

    {
        const float* gp = X + 3 * gbase;
        #pragma unroll
        for (int t = tid; t < NPG; t += 256)
            s_pos[t] = make_float4(gp[3 * t], gp[3 * t + 1], gp[3 * t + 2], 0.f);
    }
    __syncthreads();

    const float t8  = __int_as_float(T8_BITS);
    const float t10 = __int_as_float(T10_BITS);

    // 136 unordered tile-pair tasks per graph
    for (int tt = W; tt < 136; tt += 64) {
        int I, J;
        if (tt < 16)       { I = tt; J = tt; }
        else if (tt < 128) { int u = tt - 16; int bd = (u >> 4) + 1;
                             I = u & 15; J = (I + bd) & 15; }
        else               { I = tt - 128; J = I + 8; }
        if (I < 4 && J < 4) continue;          // lig-lig: no edge category
        float thr = (I >= 4 && J >= 4) ? t8 : t10;

        float4 p = s_pos[J * 32 + lane];       // lane owns column J*32+lane
        unsigned x = 0u;
        #pragma unroll
        for (int r = 0; r < 32; r++) {
            float4 a = s_pos[I * 32 + r];      // uniform broadcast load
            float dx = __fadd_rn(a.x, -p.x);
            float dy = __fadd_rn(a.y, -p.y);
            float dz = __fadd_rn(a.z, -p.z);
            float d2 = __fadd_rn(__fadd_rn(__fmul_rn(dx, dx), __fmul_rn(dy, dy)),
                                 __fmul_rn(dz, dz));
            if (d2 <= thr) x |= (1u << r);
        }
        // x (lane j): bit r = edge(I*32+r, J*32+j) = row (J*32+j), word I, bit r
        store_word(x, gbase, J, I, lane);
        if (I != J) {
            unsigned y = transpose32(x, lane); // row (I*32+lane), word J
            store_word(y, gbase, I, J, lane);
        }
    }

    // ---- last arriving block of this graph: counts from masks + scans ----
    __syncthreads();
    if (tid == 0) {
        __threadfence();
        s_last = atomicAdd(&d_arrive[b], 1);
        s_red  = 0;
    }
    __syncthreads();
    if (s_last == 7) {
        __threadfence();
        int t = tid;

        // per-row counts for rows 2t and 2t+1 via popcount of stored masks
        int vcs[2], vis[2];
        #pragma unroll
        for (int h = 0; h < 2; h++) {
            int li = 2 * t + h, i = gbase + li;
            int vc = 0, vi = 0;
            const uint4* mc = (const uint4*)&d_mask_ctx[i << 4];
            const uint4* mi = (const uint4*)&d_mask_inter[i << 4];
            if (li > LIG) {                     // protein row
                uint4 c1 = mc[1], c2 = mc[2], c3 = mc[3];
                vc = __popc(c1.x) + __popc(c1.y) + __popc(c1.z) + __popc(c1.w)
                   + __popc(c2.x) + __popc(c2.y) + __popc(c2.z) + __popc(c2.w)
                   + __popc(c3.x) + __popc(c3.y) + __popc(c3.z) + __popc(c3.w);
                uint4 i0 = mi[0];
                vi = __popc(i0.x) + __popc(i0.y) + __popc(i0.z) + __popc(i0.w);
            } else if (li >= 1 && li < LIG) {   // ligand row
                uint4 i1 = mi[1], i2 = mi[2], i3 = mi[3];
                vi = __popc(i1.x) + __popc(i1.y) + __popc(i1.z) + __popc(i1.w)
                   + __popc(i2.x) + __popc(i2.y) + __popc(i2.z) + __popc(i2.w)
                   + __popc(i3.x) + __popc(i3.y) + __popc(i3.z) + __popc(i3.w);
            }
            vcs[h] = vc; vis[h] = vi;
        }

        // ctx scan (2 rows/thread)
        {
            int s2 = vcs[0] + vcs[1];
            int x = warp_incl_scan(s2);
            if (lane == 31) sw[wid] = x;
            __syncthreads();
            if (wid == 0) {
                int v = (lane < 8) ? sw[lane] : 0;
                v = warp_incl_scan(v);
                if (lane < 8) sw[lane] = v;
            }
            __syncthreads();
            int incl = x + (wid ? sw[wid - 1] : 0);
            int excl = incl - s2;
            d_off_ctx[gbase + 2 * t]     = excl;
            d_off_ctx[gbase + 2 * t + 1] = excl + vcs[0];
            if (t == 255) d_graph_ctx[b] = incl;
            __syncthreads();
        }
        // inter scan
        {
            int s2 = vis[0] + vis[1];
            int x = warp_incl_scan(s2);
            if (lane == 31) sw[wid] = x;
            __syncthreads();
            if (wid == 0) {
                int v = (lane < 8) ? sw[lane] : 0;
                v = warp_incl_scan(v);
                if (lane < 8) sw[lane] = v;
            }
            __syncthreads();
            int incl = x + (wid ? sw[wid - 1] : 0);
            int excl = incl - s2;
            d_off_inter[gbase + 2 * t]     = excl;
            d_off_inter[gbase + 2 * t + 1] = excl + vis[0];
            if (t == 255) d_graph_inter[b] = incl;
        }

        // reduced = ligand-row (1..127) inter edges
        int vr = ((2 * t >= 1 && 2 * t < LIG) ? vis[0] : 0)
               + ((2 * t + 1 < LIG) ? vis[1] : 0);
        #pragma unroll
        for (int d = 16; d; d >>= 1) vr += __shfl_down_sync(FULL, vr, d);
        if (lane == 0 && vr) atomicAdd(&s_red, vr);
        __syncthreads();
        if (t == 0) {
            d_red_cnt[b] = s_red;
            d_arrive[b]  = 0;                   // reset for next graph replay
        }
    }
}

// ---- write: 2 rows per warp, active-word compression (proven R7 version) ----
__global__ void __launch_bounds__(512) write_kernel(float* __restrict__ out) {
    __shared__ int sgc[NB], sgi[NB], sro[NB];
    __shared__ int stc_, sti_, str_;
    int tid = threadIdx.x, lane = tid & 31, wid = tid >> 5;
    int blk  = blockIdx.x;                      // 1024 blocks
    int b    = blk >> 4;
    int s    = blk & 15;                        // slice 0..15 of graph
    int base = b << 9;

    if (wid == 0)      warp_scan64_sh(d_graph_ctx,   sgc, &stc_);
    else if (wid == 1) warp_scan64_sh(d_graph_inter, sgi, &sti_);
    else if (wid == 2) warp_scan64_sh(d_red_cnt,     sro, &str_);
    __syncthreads();

    int EcR = stc_;
    int Ec  = EcR + GFIX;
    int Ei  = sti_;
    int Er  = str_;

    int half = lane >> 4;
    int slot = lane & 15;
    int li   = s * 32 + wid * 2 + half;         // local row within graph
    int i    = base + li;

    bool prot = li > LIG;
    bool lig  = (li >= 1) && (li < LIG);
    int wIdx  = (slot < 12) ? (4 + slot) : (slot - 12);

    unsigned word = 0u;
    bool isCtx = false;
    if (prot) {
        word  = (slot < 12) ? d_mask_ctx[(i << 4) + wIdx]
                            : d_mask_inter[(i << 4) + wIdx];
        isCtx = slot < 12;
    } else if (lig && slot < 12) {
        word = d_mask_inter[(i << 4) + wIdx];
    }

    int cnt = __popc(word);
    int I   = warp_incl_scan(cnt);
    int I11 = __shfl_sync(FULL, I, 11);
    int I15 = __shfl_sync(FULL, I, 15);
    int I27 = __shfl_sync(FULL, I, 27);
    int sub0 = half ? I15 : 0;
    int sub1 = half ? I27 : I11;
    int excl = I - cnt - ((slot < 12) ? sub0 : sub1);

    int pos, colAdd;
    if (isCtx) { pos = sgc[b] + d_off_ctx[i] + excl;            colAdd = Ec; }
    else       { pos = 2 * Ec + sgi[b] + d_off_inter[i] + excl; colAdd = Ei; }

    float fi = (float)i;
    int cbase = base + wIdx * 32;
    while (word) {
        int bit = __ffs(word) - 1;
        word &= word - 1;
        out[pos]          = fi;
        out[pos + colAdd] = (float)(cbase + bit);
        pos++;
    }

    // fixed global edges: slice s handles idx in [64s, 64s+64)
    if (tid < 64) {
        int idx = s * 64 + tid;
        if (idx < GFIXPG) {
            int r, c, p;
            if (idx < GN_PER_G) {
                p = EcR + b * GN_PER_G + idx;
                if (idx < 127)        { r = 0;               c = 1 + idx; }
                else if (idx < 254)   { r = idx - 126;       c = 0; }
                else if (idx < 637)   { r = 128;             c = idx - 254 + 129; }
                else                  { r = idx - 637 + 129; c = 128; }
            } else {
                int k = idx - GN_PER_G;
                p = EcR + NB * GN_PER_G + b * 2 + k;
                r = k ? 128 : 0;
                c = k ? 0   : 128;
            }
            out[p]      = (float)(base + r);
            out[Ec + p] = (float)(base + c);
        }
    }

    // reduced arrays: contiguous chunk per slice (coalesced)
    int rcnt = d_red_cnt[b];
    int roff = sro[b];
    int chunk = (rcnt + 15) >> 4;
    int k0 = s * chunk;
    int k1 = min(k0 + chunk, rcnt);
    int base1 = 2 * Ec + 2 * Ei + roff;
    int base2 = base1 + Er;
    float fb = (float)b, fo = (float)base;
    for (int k = k0 + tid; k < k1; k += 512) {
        out[base1 + k] = fb;
        out[base2 + k] = fo;
    }
}

extern "C" void kernel_launch(void* const* d_in, const int* in_sizes, int n_in,
                              void* d_out, int out_size) {
    const float* X = (const float*)d_in[0];
    for (int k = 0; k < n_in; k++) {
        if (in_sizes[k] == 3 * NTOT) { X = (const float*)d_in[k]; break; }
    }
    float* out = (float*)d_out;
    (void)out_size;

    count_kernel<<<NB * 8, 256>>>(X);
    write_kernel<<<NTOT / 32, 512>>>(out);
}

// round 13
// speedup vs baseline: 1.1198x; 1.1198x over previous
#include <cuda_runtime.h>

#define NTOT   32768      // 64 graphs * 512 nodes
#define NB     64
#define NPG    512
#define LIG    128
#define GN_PER_G 1020
#define GG_PER_G 2
#define GFIXPG (GN_PER_G + GG_PER_G)          // 1022
#define GFIX   (NB * GFIXPG)                  // 65408
#define FULL   0xffffffffu

// d = __fsqrt_rn(d2);  d <= 8  <=>  d2 <= 64+1ulp ;  d <= 10 <=> d2 <= 100+1ulp
#define T8_BITS  0x42800001
#define T10_BITS 0x42C80001

// Packed f32x2 (Blackwell): element-wise rn, identical to scalar __fadd_rn/__fmul_rn.
#define ADD_F32X2(out, a, b) \
    asm("add.rn.f32x2 %0, %1, %2;" : "=l"(out) : "l"(a), "l"(b))
#define MUL_F32X2(out, a, b) \
    asm("mul.rn.f32x2 %0, %1, %2;" : "=l"(out) : "l"(a), "l"(b))
#define PACK_F32X2(out, lo, hi) \
    asm("mov.b64 %0, {%1, %2};" : "=l"(out) : "f"(lo), "f"(hi))
#define UNPACK_F32X2(lo, hi, in) \
    asm("mov.b64 {%0, %1}, %2;" : "=f"(lo), "=f"(hi) : "l"(in))

// 126 unordered tile pairs (I<=J), lig-lig (both<4) removed; byte = (I<<4)|J.
__device__ const unsigned char d_task_tab[126] = {
    0x04,0x05,0x06,0x07,0x08,0x09,0x0A,0x0B,0x0C,0x0D,0x0E,0x0F,
    0x14,0x15,0x16,0x17,0x18,0x19,0x1A,0x1B,0x1C,0x1D,0x1E,0x1F,
    0x24,0x25,0x26,0x27,0x28,0x29,0x2A,0x2B,0x2C,0x2D,0x2E,0x2F,
    0x34,0x35,0x36,0x37,0x38,0x39,0x3A,0x3B,0x3C,0x3D,0x3E,0x3F,
    0x44,0x45,0x46,0x47,0x48,0x49,0x4A,0x4B,0x4C,0x4D,0x4E,0x4F,
    0x55,0x56,0x57,0x58,0x59,0x5A,0x5B,0x5C,0x5D,0x5E,0x5F,
    0x66,0x67,0x68,0x69,0x6A,0x6B,0x6C,0x6D,0x6E,0x6F,
    0x77,0x78,0x79,0x7A,0x7B,0x7C,0x7D,0x7E,0x7F,
    0x88,0x89,0x8A,0x8B,0x8C,0x8D,0x8E,0x8F,
    0x99,0x9A,0x9B,0x9C,0x9D,0x9E,0x9F,
    0xAA,0xAB,0xAC,0xAD,0xAE,0xAF,
    0xBB,0xBC,0xBD,0xBE,0xBF,
    0xCC,0xCD,0xCE,0xCF,
    0xDD,0xDE,0xDF,
    0xEE,0xEF,
    0xFF
};

// Scratch (device globals; zero-initialized at load; d_arrive self-resets)
__device__ unsigned d_mask_ctx[NTOT * 16];
__device__ unsigned d_mask_inter[NTOT * 16];
__device__ int d_off_ctx[NTOT];     // within-graph exclusive row offsets
__device__ int d_off_inter[NTOT];
__device__ int d_graph_ctx[NB];
__device__ int d_graph_inter[NB];
__device__ int d_red_cnt[NB];
__device__ int d_arrive[NB];

__device__ __forceinline__ int warp_incl_scan(int x) {
    #pragma unroll
    for (int d = 1; d < 32; d <<= 1) {
        int y = __shfl_up_sync(FULL, x, d);
        if ((threadIdx.x & 31) >= d) x += y;
    }
    return x;
}

// One warp scans a 64-int array: exclusive prefix -> sh_excl[64], total -> *sh_tot.
__device__ __forceinline__ void warp_scan64_sh(const int* __restrict__ in,
                                               int* sh_excl, int* sh_tot) {
    int lane = threadIdx.x & 31;
    int v0 = in[2 * lane], v1 = in[2 * lane + 1];
    int s = v0 + v1;
    int x = warp_incl_scan(s);
    int excl = x - s;
    sh_excl[2 * lane]     = excl;
    sh_excl[2 * lane + 1] = excl + v0;
    if (lane == 31) *sh_tot = x;
}

__device__ __forceinline__ int block_excl_scan512(int v, int* sw) {
    int lane = threadIdx.x & 31, wid = threadIdx.x >> 5;
    int x = warp_incl_scan(v);
    if (lane == 31) sw[wid] = x;
    __syncthreads();
    if (wid == 0) {
        int t = (lane < 16) ? sw[lane] : 0;
        t = warp_incl_scan(t);
        if (lane < 16) sw[lane] = t;
    }
    __syncthreads();
    int add = wid ? sw[wid - 1] : 0;
    return x - v + add;
}

// 32x32 bit-matrix transpose across a warp (lane = row of bit matrix).
__device__ __forceinline__ unsigned transpose32(unsigned x, int lane) {
    #pragma unroll
    for (int s = 16; s; s >>= 1) {
        unsigned m = (s == 16) ? 0x0000FFFFu : (s == 8) ? 0x00FF00FFu :
                     (s == 4)  ? 0x0F0F0F0Fu : (s == 2) ? 0x33333333u : 0x55555555u;
        unsigned q = __shfl_xor_sync(FULL, x, s);
        x = (lane & s) ? ((x & ~m) | ((q & ~m) >> s))
                       : ((x & m)  | ((q & m)  << s));
    }
    return x;
}

// Store word for (rowTile R, colWord C) with all boundary fixes applied.
__device__ __forceinline__ void store_word(unsigned w, int gbase, int R, int C, int lane) {
    if (C == 0 || C == 4) w &= ~1u;              // global columns 0 / 128
    if ((R == 0 || R == 4) && lane == 0) w = 0u; // global rows 0 / 128
    if (R == C) w &= ~(1u << lane);              // self pairs on diagonal
    int idx = ((gbase + R * 32 + lane) << 4) + C;
    if (R < 4 || C < 4) d_mask_inter[idx] = w;   // lig-lig tiles never reach here
    else                d_mask_ctx[idx]   = w;
}

// ---- count: symmetric tile-pair enumeration, balanced task table, f32x2 ----
__global__ void __launch_bounds__(512) count_kernel(const float* __restrict__ X) {
    __shared__ float4 s_pos[NPG];
    __shared__ int sw[16];
    __shared__ int s_last, s_red;
    int tid  = threadIdx.x, lane = tid & 31, wid = tid >> 5;
    int blk  = blockIdx.x;                     // 256 blocks, 4 per graph
    int b    = blk >> 2;
    int gbase = b << 9;
    int W    = (blk & 3) * 16 + wid;           // warp id within graph, 0..63

    {
        const float* gp = X + 3 * gbase;
        int t = tid;
        s_pos[t] = make_float4(gp[3 * t], gp[3 * t + 1], gp[3 * t + 2], 0.f);
    }
    __syncthreads();

    const float t8  = __int_as_float(T8_BITS);
    const float t10 = __int_as_float(T10_BITS);

    // 126 valid tile-pair tasks per graph: warps get at most 2 each
    for (int tt = W; tt < 126; tt += 64) {
        int ij = d_task_tab[tt];
        int I = ij >> 4, J = ij & 15;
        float thr = (I >= 4) ? t8 : t10;       // I>=4 && J>=I>=4 -> prot-prot

        float4 p = s_pos[J * 32 + lane];       // lane owns column J*32+lane
        unsigned long long npxy;
        PACK_F32X2(npxy, -p.x, -p.y);
        float npz = -p.z;

        unsigned x = 0u;
        #pragma unroll
        for (int r = 0; r < 32; r++) {
            float4 a = s_pos[I * 32 + r];      // uniform broadcast LDS.128
            unsigned long long axy, dxy, d2xy;
            PACK_F32X2(axy, a.x, a.y);
            ADD_F32X2(dxy, axy, npxy);
            MUL_F32X2(d2xy, dxy, dxy);
            float dz = __fadd_rn(a.z, npz);
            float dx2, dy2;
            UNPACK_F32X2(dx2, dy2, d2xy);
            float d2 = __fadd_rn(__fadd_rn(dx2, dy2), __fmul_rn(dz, dz));
            if (d2 <= thr) x |= (1u << r);
        }
        // x (lane j): bit r = edge(I*32+r, J*32+j) = row (J*32+j), word I, bit r
        store_word(x, gbase, J, I, lane);
        if (I != J) {
            unsigned y = transpose32(x, lane); // row (I*32+lane), word J
            store_word(y, gbase, I, J, lane);
        }
    }

    // ---- last arriving block of this graph: counts from masks + scans ----
    __syncthreads();
    if (tid == 0) {
        __threadfence();
        s_last = atomicAdd(&d_arrive[b], 1);
        s_red  = 0;
    }
    __syncthreads();
    if (s_last == 3) {
        __threadfence();
        int t = tid, i = gbase + t;

        int vc = 0, vi = 0;
        const uint4* mc = (const uint4*)&d_mask_ctx[i << 4];
        const uint4* mi = (const uint4*)&d_mask_inter[i << 4];
        if (t > LIG) {                          // protein row
            uint4 c1 = mc[1], c2 = mc[2], c3 = mc[3];
            vc = __popc(c1.x) + __popc(c1.y) + __popc(c1.z) + __popc(c1.w)
               + __popc(c2.x) + __popc(c2.y) + __popc(c2.z) + __popc(c2.w)
               + __popc(c3.x) + __popc(c3.y) + __popc(c3.z) + __popc(c3.w);
            uint4 i0 = mi[0];
            vi = __popc(i0.x) + __popc(i0.y) + __popc(i0.z) + __popc(i0.w);
        } else if (t >= 1 && t < LIG) {         // ligand row
            uint4 i1 = mi[1], i2 = mi[2], i3 = mi[3];
            vi = __popc(i1.x) + __popc(i1.y) + __popc(i1.z) + __popc(i1.w)
               + __popc(i2.x) + __popc(i2.y) + __popc(i2.z) + __popc(i2.w)
               + __popc(i3.x) + __popc(i3.y) + __popc(i3.z) + __popc(i3.w);
        }

        int ec = block_excl_scan512(vc, sw);
        d_off_ctx[i] = ec;
        if (t == 511) d_graph_ctx[b] = ec + vc;
        __syncthreads();

        int ei = block_excl_scan512(vi, sw);
        d_off_inter[i] = ei;
        if (t == 511) d_graph_inter[b] = ei + vi;

        int vr = (t >= 1 && t < LIG) ? vi : 0;  // reduced = ligand-row inter edges
        #pragma unroll
        for (int d = 16; d; d >>= 1) vr += __shfl_down_sync(FULL, vr, d);
        if (lane == 0 && vr) atomicAdd(&s_red, vr);
        __syncthreads();
        if (t == 0) {
            d_red_cnt[b] = s_red;
            d_arrive[b]  = 0;                   // reset for next graph replay
        }
    }
}

// ---- write: 2 rows per warp, active-word compression (proven R7/R11 version) ----
__global__ void __launch_bounds__(512) write_kernel(float* __restrict__ out) {
    __shared__ int sgc[NB], sgi[NB], sro[NB];
    __shared__ int stc_, sti_, str_;
    int tid = threadIdx.x, lane = tid & 31, wid = tid >> 5;
    int blk  = blockIdx.x;                      // 1024 blocks
    int b    = blk >> 4;
    int s    = blk & 15;                        // slice 0..15 of graph
    int base = b << 9;

    if (wid == 0)      warp_scan64_sh(d_graph_ctx,   sgc, &stc_);
    else if (wid == 1) warp_scan64_sh(d_graph_inter, sgi, &sti_);
    else if (wid == 2) warp_scan64_sh(d_red_cnt,     sro, &str_);
    __syncthreads();

    int EcR = stc_;
    int Ec  = EcR + GFIX;
    int Ei  = sti_;
    int Er  = str_;

    int half = lane >> 4;
    int slot = lane & 15;
    int li   = s * 32 + wid * 2 + half;         // local row within graph
    int i    = base + li;

    bool prot = li > LIG;
    bool lig  = (li >= 1) && (li < LIG);
    int wIdx  = (slot < 12) ? (4 + slot) : (slot - 12);

    unsigned word = 0u;
    bool isCtx = false;
    if (prot) {
        word  = (slot < 12) ? d_mask_ctx[(i << 4) + wIdx]
                            : d_mask_inter[(i << 4) + wIdx];
        isCtx = slot < 12;
    } else if (lig && slot < 12) {
        word = d_mask_inter[(i << 4) + wIdx];
    }

    int cnt = __popc(word);
    int I   = warp_incl_scan(cnt);
    int I11 = __shfl_sync(FULL, I, 11);
    int I15 = __shfl_sync(FULL, I, 15);
    int I27 = __shfl_sync(FULL, I, 27);
    int sub0 = half ? I15 : 0;
    int sub1 = half ? I27 : I11;
    int excl = I - cnt - ((slot < 12) ? sub0 : sub1);

    int pos, colAdd;
    if (isCtx) { pos = sgc[b] + d_off_ctx[i] + excl;            colAdd = Ec; }
    else       { pos = 2 * Ec + sgi[b] + d_off_inter[i] + excl; colAdd = Ei; }

    float fi = (float)i;
    int cbase = base + wIdx * 32;
    while (word) {
        int bit = __ffs(word) - 1;
        word &= word - 1;
        out[pos]          = fi;
        out[pos + colAdd] = (float)(cbase + bit);
        pos++;
    }

    // fixed global edges: slice s handles idx in [64s, 64s+64)
    if (tid < 64) {
        int idx = s * 64 + tid;
        if (idx < GFIXPG) {
            int r, c, p;
            if (idx < GN_PER_G) {
                p = EcR + b * GN_PER_G + idx;
                if (idx < 127)        { r = 0;               c = 1 + idx; }
                else if (idx < 254)   { r = idx - 126;       c = 0; }
                else if (idx < 637)   { r = 128;             c = idx - 254 + 129; }
                else                  { r = idx - 637 + 129; c = 128; }
            } else {
                int k = idx - GN_PER_G;
                p = EcR + NB * GN_PER_G + b * 2 + k;
                r = k ? 128 : 0;
                c = k ? 0   : 128;
            }
            out[p]      = (float)(base + r);
            out[Ec + p] = (float)(base + c);
        }
    }

    // reduced arrays: contiguous chunk per slice (coalesced)
    int rcnt = d_red_cnt[b];
    int roff = sro[b];
    int chunk = (rcnt + 15) >> 4;
    int k0 = s * chunk;
    int k1 = min(k0 + chunk, rcnt);
    int base1 = 2 * Ec + 2 * Ei + roff;
    int base2 = base1 + Er;
    float fb = (float)b, fo = (float)base;
    for (int k = k0 + tid; k < k1; k += 512) {
        out[base1 + k] = fb;
        out[base2 + k] = fo;
    }
}

extern "C" void kernel_launch(void* const* d_in, const int* in_sizes, int n_in,
                              void* d_out, int out_size) {
    const float* X = (const float*)d_in[0];
    for (int k = 0; k < n_in; k++) {
        if (in_sizes[k] == 3 * NTOT) { X = (const float*)d_in[k]; break; }
    }
    float* out = (float*)d_out;
    (void)out_size;

    count_kernel<<<NB * 4, 512>>>(X);
    write_kernel<<<NTOT / 32, 512>>>(out);
}

// round 14
// speedup vs baseline: 1.2183x; 1.0880x over previous
#include <cuda_runtime.h>

#define NTOT   32768      // 64 graphs * 512 nodes
#define NB     64
#define NPG    512
#define LIG    128
#define GN_PER_G 1020
#define GG_PER_G 2
#define GFIXPG (GN_PER_G + GG_PER_G)          // 1022
#define GFIX   (NB * GFIXPG)                  // 65408
#define FULL   0xffffffffu

// d = __fsqrt_rn(d2);  d <= 8  <=>  d2 <= 64+1ulp ;  d <= 10 <=> d2 <= 100+1ulp
#define T8_BITS  0x42800001
#define T10_BITS 0x42C80001

// Packed f32x2 (Blackwell): element-wise rn, identical to scalar __fadd_rn/__fmul_rn.
#define ADD_F32X2(out, a, b) \
    asm("add.rn.f32x2 %0, %1, %2;" : "=l"(out) : "l"(a), "l"(b))
#define MUL_F32X2(out, a, b) \
    asm("mul.rn.f32x2 %0, %1, %2;" : "=l"(out) : "l"(a), "l"(b))
#define PACK_F32X2(out, lo, hi) \
    asm("mov.b64 %0, {%1, %2};" : "=l"(out) : "f"(lo), "f"(hi))
#define UNPACK_F32X2(lo, hi, in) \
    asm("mov.b64 {%0, %1}, %2;" : "=f"(lo), "=f"(hi) : "l"(in))

// 126 unordered tile pairs (I<=J), lig-lig (both<4) removed; byte = (I<<4)|J.
__device__ const unsigned char d_task_tab[126] = {
    0x04,0x05,0x06,0x07,0x08,0x09,0x0A,0x0B,0x0C,0x0D,0x0E,0x0F,
    0x14,0x15,0x16,0x17,0x18,0x19,0x1A,0x1B,0x1C,0x1D,0x1E,0x1F,
    0x24,0x25,0x26,0x27,0x28,0x29,0x2A,0x2B,0x2C,0x2D,0x2E,0x2F,
    0x34,0x35,0x36,0x37,0x38,0x39,0x3A,0x3B,0x3C,0x3D,0x3E,0x3F,
    0x44,0x45,0x46,0x47,0x48,0x49,0x4A,0x4B,0x4C,0x4D,0x4E,0x4F,
    0x55,0x56,0x57,0x58,0x59,0x5A,0x5B,0x5C,0x5D,0x5E,0x5F,
    0x66,0x67,0x68,0x69,0x6A,0x6B,0x6C,0x6D,0x6E,0x6F,
    0x77,0x78,0x79,0x7A,0x7B,0x7C,0x7D,0x7E,0x7F,
    0x88,0x89,0x8A,0x8B,0x8C,0x8D,0x8E,0x8F,
    0x99,0x9A,0x9B,0x9C,0x9D,0x9E,0x9F,
    0xAA,0xAB,0xAC,0xAD,0xAE,0xAF,
    0xBB,0xBC,0xBD,0xBE,0xBF,
    0xCC,0xCD,0xCE,0xCF,
    0xDD,0xDE,0xDF,
    0xEE,0xEF,
    0xFF
};

// Scratch (device globals; zero-initialized at load; d_arrive self-resets)
__device__ unsigned d_mask_ctx[NTOT * 16];
__device__ unsigned d_mask_inter[NTOT * 16];
__device__ int d_off_ctx[NTOT];     // within-graph exclusive row offsets
__device__ int d_off_inter[NTOT];
__device__ int d_graph_ctx[NB];
__device__ int d_graph_inter[NB];
__device__ int d_red_cnt[NB];
__device__ int d_arrive[NB];

__device__ __forceinline__ int warp_incl_scan(int x) {
    #pragma unroll
    for (int d = 1; d < 32; d <<= 1) {
        int y = __shfl_up_sync(FULL, x, d);
        if ((threadIdx.x & 31) >= d) x += y;
    }
    return x;
}

// One warp scans a 64-int array: exclusive prefix -> sh_excl[64], total -> *sh_tot.
__device__ __forceinline__ void warp_scan64_sh(const int* __restrict__ in,
                                               int* sh_excl, int* sh_tot) {
    int lane = threadIdx.x & 31;
    int v0 = in[2 * lane], v1 = in[2 * lane + 1];
    int s = v0 + v1;
    int x = warp_incl_scan(s);
    int excl = x - s;
    sh_excl[2 * lane]     = excl;
    sh_excl[2 * lane + 1] = excl + v0;
    if (lane == 31) *sh_tot = x;
}

__device__ __forceinline__ int block_excl_scan512(int v, int* sw) {
    int lane = threadIdx.x & 31, wid = threadIdx.x >> 5;
    int x = warp_incl_scan(v);
    if (lane == 31) sw[wid] = x;
    __syncthreads();
    if (wid == 0) {
        int t = (lane < 16) ? sw[lane] : 0;
        t = warp_incl_scan(t);
        if (lane < 16) sw[lane] = t;
    }
    __syncthreads();
    int add = wid ? sw[wid - 1] : 0;
    return x - v + add;
}

// 32x32 bit-matrix transpose across a warp (lane = row of bit matrix).
__device__ __forceinline__ unsigned transpose32(unsigned x, int lane) {
    #pragma unroll
    for (int s = 16; s; s >>= 1) {
        unsigned m = (s == 16) ? 0x0000FFFFu : (s == 8) ? 0x00FF00FFu :
                     (s == 4)  ? 0x0F0F0F0Fu : (s == 2) ? 0x33333333u : 0x55555555u;
        unsigned q = __shfl_xor_sync(FULL, x, s);
        x = (lane & s) ? ((x & ~m) | ((q & ~m) >> s))
                       : ((x & m)  | ((q & m)  << s));
    }
    return x;
}

// Store word for (rowTile R, colWord C) with all boundary fixes applied.
__device__ __forceinline__ void store_word(unsigned w, int gbase, int R, int C, int lane) {
    if (C == 0 || C == 4) w &= ~1u;              // global columns 0 / 128
    if ((R == 0 || R == 4) && lane == 0) w = 0u; // global rows 0 / 128
    if (R == C) w &= ~(1u << lane);              // self pairs on diagonal
    int idx = ((gbase + R * 32 + lane) << 4) + C;
    if (R < 4 || C < 4) d_mask_inter[idx] = w;   // lig-lig tiles never reach here
    else                d_mask_ctx[idx]   = w;
}

// ---- count: symmetric tile-pair enumeration, balanced task table, f32x2 ----
__global__ void __launch_bounds__(512) count_kernel(const float* __restrict__ X) {
    __shared__ float4 s_pos[NPG];
    __shared__ int sw[16];
    __shared__ int s_last, s_red;
    int tid  = threadIdx.x, lane = tid & 31, wid = tid >> 5;
    int blk  = blockIdx.x;                     // 256 blocks, 4 per graph
    int b    = blk >> 2;
    int gbase = b << 9;
    int W    = (blk & 3) * 16 + wid;           // warp id within graph, 0..63

    {
        const float* gp = X + 3 * gbase;
        int t = tid;
        s_pos[t] = make_float4(gp[3 * t], gp[3 * t + 1], gp[3 * t + 2], 0.f);
    }
    __syncthreads();

    const float t8  = __int_as_float(T8_BITS);
    const float t10 = __int_as_float(T10_BITS);

    // 126 valid tile-pair tasks per graph: warps get at most 2 each
    for (int tt = W; tt < 126; tt += 64) {
        int ij = d_task_tab[tt];
        int I = ij >> 4, J = ij & 15;
        float thr = (I >= 4) ? t8 : t10;       // I>=4 && J>=I>=4 -> prot-prot

        float4 p = s_pos[J * 32 + lane];       // lane owns column J*32+lane
        unsigned long long npxy;
        PACK_F32X2(npxy, -p.x, -p.y);
        float npz = -p.z;

        unsigned x = 0u;
        #pragma unroll
        for (int r = 0; r < 32; r++) {
            float4 a = s_pos[I * 32 + r];      // uniform broadcast LDS.128
            unsigned long long axy, dxy, d2xy;
            PACK_F32X2(axy, a.x, a.y);
            ADD_F32X2(dxy, axy, npxy);
            MUL_F32X2(d2xy, dxy, dxy);
            float dz = __fadd_rn(a.z, npz);
            float dx2, dy2;
            UNPACK_F32X2(dx2, dy2, d2xy);
            float d2 = __fadd_rn(__fadd_rn(dx2, dy2), __fmul_rn(dz, dz));
            if (d2 <= thr) x |= (1u << r);
        }
        // x (lane j): bit r = edge(I*32+r, J*32+j) = row (J*32+j), word I, bit r
        store_word(x, gbase, J, I, lane);
        if (I != J) {
            unsigned y = transpose32(x, lane); // row (I*32+lane), word J
            store_word(y, gbase, I, J, lane);
        }
    }

    // ---- last arriving block of this graph: counts from masks + scans ----
    __syncthreads();
    if (tid == 0) {
        __threadfence();
        s_last = atomicAdd(&d_arrive[b], 1);
        s_red  = 0;
    }
    __syncthreads();
    if (s_last == 3) {
        __threadfence();
        int t = tid, i = gbase + t;

        int vc = 0, vi = 0;
        const uint4* mc = (const uint4*)&d_mask_ctx[i << 4];
        const uint4* mi = (const uint4*)&d_mask_inter[i << 4];
        if (t > LIG) {                          // protein row
            uint4 c1 = mc[1], c2 = mc[2], c3 = mc[3];
            vc = __popc(c1.x) + __popc(c1.y) + __popc(c1.z) + __popc(c1.w)
               + __popc(c2.x) + __popc(c2.y) + __popc(c2.z) + __popc(c2.w)
               + __popc(c3.x) + __popc(c3.y) + __popc(c3.z) + __popc(c3.w);
            uint4 i0 = mi[0];
            vi = __popc(i0.x) + __popc(i0.y) + __popc(i0.z) + __popc(i0.w);
        } else if (t >= 1 && t < LIG) {         // ligand row
            uint4 i1 = mi[1], i2 = mi[2], i3 = mi[3];
            vi = __popc(i1.x) + __popc(i1.y) + __popc(i1.z) + __popc(i1.w)
               + __popc(i2.x) + __popc(i2.y) + __popc(i2.z) + __popc(i2.w)
               + __popc(i3.x) + __popc(i3.y) + __popc(i3.z) + __popc(i3.w);
        }

        int ec = block_excl_scan512(vc, sw);
        d_off_ctx[i] = ec;
        if (t == 511) d_graph_ctx[b] = ec + vc;
        __syncthreads();

        int ei = block_excl_scan512(vi, sw);
        d_off_inter[i] = ei;
        if (t == 511) d_graph_inter[b] = ei + vi;

        int vr = (t >= 1 && t < LIG) ? vi : 0;  // reduced = ligand-row inter edges
        #pragma unroll
        for (int d = 16; d; d >>= 1) vr += __shfl_down_sync(FULL, vr, d);
        if (lane == 0 && vr) atomicAdd(&s_red, vr);
        __syncthreads();
        if (t == 0) {
            d_red_cnt[b] = s_red;
            d_arrive[b]  = 0;                   // reset for next graph replay
        }
    }
}

// ---- write: 2 rows per warp, active-word compression (proven R7/R11 version) ----
__global__ void __launch_bounds__(512) write_kernel(float* __restrict__ out) {
    __shared__ int sgc[NB], sgi[NB], sro[NB];
    __shared__ int stc_, sti_, str_;
    int tid = threadIdx.x, lane = tid & 31, wid = tid >> 5;
    int blk  = blockIdx.x;                      // 1024 blocks
    int b    = blk >> 4;
    int s    = blk & 15;                        // slice 0..15 of graph
    int base = b << 9;

    if (wid == 0)      warp_scan64_sh(d_graph_ctx,   sgc, &stc_);
    else if (wid == 1) warp_scan64_sh(d_graph_inter, sgi, &sti_);
    else if (wid == 2) warp_scan64_sh(d_red_cnt,     sro, &str_);
    __syncthreads();

    int EcR = stc_;
    int Ec  = EcR + GFIX;
    int Ei  = sti_;
    int Er  = str_;

    int half = lane >> 4;
    int slot = lane & 15;
    int li   = s * 32 + wid * 2 + half;         // local row within graph
    int i    = base + li;

    bool prot = li > LIG;
    bool lig  = (li >= 1) && (li < LIG);
    int wIdx  = (slot < 12) ? (4 + slot) : (slot - 12);

    unsigned word = 0u;
    bool isCtx = false;
    if (prot) {
        word  = (slot < 12) ? d_mask_ctx[(i << 4) + wIdx]
                            : d_mask_inter[(i << 4) + wIdx];
        isCtx = slot < 12;
    } else if (lig && slot < 12) {
        word = d_mask_inter[(i << 4) + wIdx];
    }

    int cnt = __popc(word);
    int I   = warp_incl_scan(cnt);
    int I11 = __shfl_sync(FULL, I, 11);
    int I15 = __shfl_sync(FULL, I, 15);
    int I27 = __shfl_sync(FULL, I, 27);
    int sub0 = half ? I15 : 0;
    int sub1 = half ? I27 : I11;
    int excl = I - cnt - ((slot < 12) ? sub0 : sub1);

    int pos, colAdd;
    if (isCtx) { pos = sgc[b] + d_off_ctx[i] + excl;            colAdd = Ec; }
    else       { pos = 2 * Ec + sgi[b] + d_off_inter[i] + excl; colAdd = Ei; }

    float fi = (float)i;
    int cbase = base + wIdx * 32;
    while (word) {
        int bit = __ffs(word) - 1;
        word &= word - 1;
        out[pos]          = fi;
        out[pos + colAdd] = (float)(cbase + bit);
        pos++;
    }

    // fixed global edges: slice s handles idx in [64s, 64s+64)
    if (tid < 64) {
        int idx = s * 64 + tid;
        if (idx < GFIXPG) {
            int r, c, p;
            if (idx < GN_PER_G) {
                p = EcR + b * GN_PER_G + idx;
                if (idx < 127)        { r = 0;               c = 1 + idx; }
                else if (idx < 254)   { r = idx - 126;       c = 0; }
                else if (idx < 637)   { r = 128;             c = idx - 254 + 129; }
                else                  { r = idx - 637 + 129; c = 128; }
            } else {
                int k = idx - GN_PER_G;
                p = EcR + NB * GN_PER_G + b * 2 + k;
                r = k ? 128 : 0;
                c = k ? 0   : 128;
            }
            out[p]      = (float)(base + r);
            out[Ec + p] = (float)(base + c);
        }
    }

    // reduced arrays: contiguous chunk per slice (coalesced)
    int rcnt = d_red_cnt[b];
    int roff = sro[b];
    int chunk = (rcnt + 15) >> 4;
    int k0 = s * chunk;
    int k1 = min(k0 + chunk, rcnt);
    int base1 = 2 * Ec + 2 * Ei + roff;
    int base2 = base1 + Er;
    float fb = (float)b, fo = (float)base;
    for (int k = k0 + tid; k < k1; k += 512) {
        out[base1 + k] = fb;
        out[base2 + k] = fo;
    }
}

extern "C" void kernel_launch(void* const* d_in, const int* in_sizes, int n_in,
                              void* d_out, int out_size) {
    const float* X = (const float*)d_in[0];
    for (int k = 0; k < n_in; k++) {
        if (in_sizes[k] == 3 * NTOT) { X = (const float*)d_in[k]; break; }
    }
    float* out = (float*)d_out;
    (void)out_size;

    count_kernel<<<NB * 4, 512>>>(X);
    write_kernel<<<NTOT / 32, 512>>>(out);
}